// round 4
// baseline (speedup 1.0000x reference)
#include <cuda_runtime.h>
#include <cuda_bf16.h>
#include <cstdint>

// adaptive_avg_pool2d(x[32,2048,28,28], 7) -> out[32,49,2048]
// linspace(0,28,8) = 0,4,...,28 => exact uniform 4x4 windows.
//
// R4: kill wave quantization. R3 ran 2048 blocks over a 1184-block-capacity
// chip = 1.73 waves -> avg mem utilization ~77% (measured DRAM 76%).
// TILE_C 32 -> 64 gives 1024 blocks = single resident wave (8 blocks/SM,
// 20.5KB smem, regs<=32, 64 warps/SM).

#define CCH    2048
#define HW     784
#define NQ     196       // float4 per 28x28 plane
#define TILE_C 64
#define ACC_STRIDE 57    // odd stride: conflict-free transposed readout
#define STG_STRIDE 200   // per-warp stage stride

__global__ __launch_bounds__(256, 8)
void upp_pool_kernel(const float* __restrict__ x, float* __restrict__ out) {
    __shared__ float stage[8 * STG_STRIDE];     // 6400 B
    __shared__ float acc[TILE_C * ACC_STRIDE];  // 14592 B

    const int b    = blockIdx.y;
    const int c0   = blockIdx.x * TILE_C;
    const int tid  = threadIdx.x;
    const int warp = tid >> 5;
    const int lane = tid & 31;
    const int wbase = warp * STG_STRIDE;

    // Per-lane bin offsets, hoisted out of the channel loop.
    // bin b0 = lane (0..31); bin b1 = lane+32 (valid if < 49, i.e. lane < 17)
    const int b0 = lane;
    const int o0 = 28 * (b0 / 7) + (b0 % 7);
    const int b1 = lane + 32;
    const int o1 = 28 * (b1 / 7) + (b1 % 7);

    // Each warp owns 8 consecutive channels of this 64-channel tile.
    #pragma unroll
    for (int cw = 0; cw < 8; ++cw) {
        const int c_local = warp * 8 + cw;
        const size_t plane_off = ((size_t)(b * CCH + c0 + c_local)) * HW;
        const float4* __restrict__ plane =
            reinterpret_cast<const float4*>(x + plane_off);

        // Phase 1: coalesced loads -> horizontal partials -> stage (plain STS)
        #pragma unroll
        for (int k = 0; k < 7; ++k) {
            const int q = lane + 32 * k;
            if (q < NQ) {
                const float4 v = plane[q];   // LDG.128, fully coalesced
                stage[wbase + q] = (v.x + v.y + v.z + v.w) * 0.0625f;
            }
        }
        __syncwarp();

        // Phase 2: vertical reduce over 4 rows per bin (warp-local, no atomics)
        {
            const float r0 = stage[wbase + o0]      + stage[wbase + o0 + 7] +
                             stage[wbase + o0 + 14] + stage[wbase + o0 + 21];
            acc[c_local * ACC_STRIDE + b0] = r0;
        }
        if (lane < 17) {
            const float r1 = stage[wbase + o1]      + stage[wbase + o1 + 7] +
                             stage[wbase + o1 + 14] + stage[wbase + o1 + 21];
            acc[c_local * ACC_STRIDE + b1] = r1;
        }
        __syncwarp();   // WAR: stage reused by next channel
    }
    __syncthreads();

    // out[b, p, c0+c] = acc[c*57 + p]; contiguous in c -> coalesced stores
    float* __restrict__ ob = out + (size_t)b * 49 * CCH + c0;
    #pragma unroll
    for (int i = tid; i < 49 * TILE_C; i += 256) {
        const int p = i >> 6;              // 0..48
        const int c = i & (TILE_C - 1);    // 0..63
        ob[p * CCH + c] = acc[c * ACC_STRIDE + p];
    }
}

extern "C" void kernel_launch(void* const* d_in, const int* in_sizes, int n_in,
                              void* d_out, int out_size) {
    const float* x = (const float*)d_in[0];
    float* out = (float*)d_out;
    dim3 grid(CCH / TILE_C, 32);   // (32, 32) = 1024 blocks: single wave
    upp_pool_kernel<<<grid, 256>>>(x, out);
}

// round 5
// speedup vs baseline: 1.0629x; 1.0629x over previous
#include <cuda_runtime.h>
#include <cuda_bf16.h>
#include <cstdint>

// adaptive_avg_pool2d(x[32,2048,28,28], 7) -> out[32,49,2048]
// linspace(0,28,8) = 0,4,...,28 => exact uniform 4x4 windows.
//
// R5: maximal granularity to kill the scheduler drain tail (R4's single long
// wave lost ~28% to end-of-kernel idle). TILE_C=8: one channel per warp,
// 8192 short blocks (~1.5us each) -> greedy block scheduler keeps SMs busy
// until the last moment. No acc zero-init, no channel loop, 8.2KB smem,
// 8 blocks/SM, regs<=32.

#define CCH    2048
#define HW     784
#define NQ     196       // float4 per 28x28 plane
#define TILE_C 8
#define ACC_STRIDE 57    // odd stride: conflict-free transposed readout
#define STG_STRIDE 200   // per-warp stage stride

__global__ __launch_bounds__(256, 8)
void upp_pool_kernel(const float* __restrict__ x, float* __restrict__ out) {
    __shared__ float stage[8 * STG_STRIDE];     // 6400 B
    __shared__ float acc[TILE_C * ACC_STRIDE];  // 1824 B

    const int b    = blockIdx.y;
    const int c0   = blockIdx.x * TILE_C;
    const int tid  = threadIdx.x;
    const int warp = tid >> 5;     // = c_local: one channel per warp
    const int lane = tid & 31;
    const int wbase = warp * STG_STRIDE;

    // Per-lane bin offsets. bin b0 = lane (0..31); bin b1 = lane+32 (<49)
    const int b0 = lane;
    const int o0 = 28 * (b0 / 7) + (b0 % 7);
    const int b1 = lane + 32;
    const int o1 = 28 * (b1 / 7) + (b1 % 7);

    const size_t plane_off = ((size_t)(b * CCH + c0 + warp)) * HW;
    const float4* __restrict__ plane =
        reinterpret_cast<const float4*>(x + plane_off);

    // Phase 1: coalesced LDG.128 -> horizontal partials -> stage (plain STS)
    #pragma unroll
    for (int k = 0; k < 7; ++k) {
        const int q = lane + 32 * k;
        if (q < NQ) {
            const float4 v = plane[q];
            stage[wbase + q] = (v.x + v.y + v.z + v.w) * 0.0625f;
        }
    }
    __syncwarp();

    // Phase 2: vertical reduce over 4 rows per bin (warp-local, no atomics).
    // Every (c,bin) slot written exactly once -> no zero-init needed.
    {
        const float r0 = stage[wbase + o0]      + stage[wbase + o0 + 7] +
                         stage[wbase + o0 + 14] + stage[wbase + o0 + 21];
        acc[warp * ACC_STRIDE + b0] = r0;
    }
    if (lane < 17) {
        const float r1 = stage[wbase + o1]      + stage[wbase + o1 + 7] +
                         stage[wbase + o1 + 14] + stage[wbase + o1 + 21];
        acc[warp * ACC_STRIDE + b1] = r1;
    }
    __syncthreads();

    // out[b, p, c0+c] = acc[c*57 + p]; 8 contiguous floats per p-row
    // (one 32B sector; adjacent blockIdx.x fills neighboring sectors).
    float* __restrict__ ob = out + (size_t)b * 49 * CCH + c0;
    #pragma unroll
    for (int i = tid; i < 49 * TILE_C; i += 256) {
        const int p = i >> 3;              // 0..48
        const int c = i & (TILE_C - 1);    // 0..7
        ob[p * CCH + c] = acc[c * ACC_STRIDE + p];
    }
}

extern "C" void kernel_launch(void* const* d_in, const int* in_sizes, int n_in,
                              void* d_out, int out_size) {
    const float* x = (const float*)d_in[0];
    float* out = (float*)d_out;
    dim3 grid(CCH / TILE_C, 32);   // (256, 32) = 8192 short blocks
    upp_pool_kernel<<<grid, 256>>>(x, out);
}

// round 6
// speedup vs baseline: 1.1333x; 1.0662x over previous
#include <cuda_runtime.h>
#include <cuda_bf16.h>
#include <cstdint>

// adaptive_avg_pool2d(x[32,2048,28,28], 7) -> out[32,49,2048]
// linspace(0,28,8) = 0,4,...,28 => exact uniform 4x4 windows.
//
// R6: trade occupancy for MLP. R5's launch_bounds(256,8) capped regs at 32,
// preventing ptxas from front-batching the 7 LDG.128 (MLP~2/warp, borderline
// for DRAM saturation). Now launch_bounds(256,6) -> 42 regs: all 7 float4
// loaded up-front into registers (MLP=7), 48 warps/SM -> ~336 loads in
// flight per SM (~2.6x saturation requirement). Grid stays 8192 short
// blocks (tail stays tiny).

#define CCH    2048
#define HW     784
#define NQ     196       // float4 per 28x28 plane
#define TILE_C 8
#define ACC_STRIDE 57    // odd stride: conflict-free transposed readout
#define STG_STRIDE 200   // per-warp stage stride

__global__ __launch_bounds__(256, 6)
void upp_pool_kernel(const float* __restrict__ x, float* __restrict__ out) {
    __shared__ float stage[8 * STG_STRIDE];     // 6400 B
    __shared__ float acc[TILE_C * ACC_STRIDE];  // 1824 B

    const int b    = blockIdx.y;
    const int c0   = blockIdx.x * TILE_C;
    const int tid  = threadIdx.x;
    const int warp = tid >> 5;     // = c_local: one channel per warp
    const int lane = tid & 31;
    const int wbase = warp * STG_STRIDE;

    const size_t plane_off = ((size_t)(b * CCH + c0 + warp)) * HW;
    const float4* __restrict__ plane =
        reinterpret_cast<const float4*>(x + plane_off) + lane;

    // Phase 1: front-batch ALL 7 LDG.128 before any consumption (MLP=7).
    // q = lane + 32k; last one valid only for lane < 4 (q < 196).
    float4 v0 = plane[0];
    float4 v1 = plane[32];
    float4 v2 = plane[64];
    float4 v3 = plane[96];
    float4 v4 = plane[128];
    float4 v5 = plane[160];
    float4 v6 = make_float4(0.f, 0.f, 0.f, 0.f);
    if (lane < 4) v6 = plane[192];

    // Horizontal partials -> per-warp stage (plain STS, conflict-free)
    stage[wbase + lane +   0] = (v0.x + v0.y + v0.z + v0.w) * 0.0625f;
    stage[wbase + lane +  32] = (v1.x + v1.y + v1.z + v1.w) * 0.0625f;
    stage[wbase + lane +  64] = (v2.x + v2.y + v2.z + v2.w) * 0.0625f;
    stage[wbase + lane +  96] = (v3.x + v3.y + v3.z + v3.w) * 0.0625f;
    stage[wbase + lane + 128] = (v4.x + v4.y + v4.z + v4.w) * 0.0625f;
    stage[wbase + lane + 160] = (v5.x + v5.y + v5.z + v5.w) * 0.0625f;
    if (lane < 4)
        stage[wbase + lane + 192] = (v6.x + v6.y + v6.z + v6.w) * 0.0625f;
    __syncwarp();

    // Phase 2: vertical reduce over 4 rows per bin (warp-local, no atomics).
    // bin b0 = lane (0..31); bin b1 = lane+32 (valid if < 49)
    const int b0 = lane;
    const int o0 = wbase + 28 * (b0 / 7) + (b0 % 7);
    acc[warp * ACC_STRIDE + b0] =
        stage[o0] + stage[o0 + 7] + stage[o0 + 14] + stage[o0 + 21];
    if (lane < 17) {
        const int b1 = lane + 32;
        const int o1 = wbase + 28 * (b1 / 7) + (b1 % 7);
        acc[warp * ACC_STRIDE + b1] =
            stage[o1] + stage[o1 + 7] + stage[o1 + 14] + stage[o1 + 21];
    }
    __syncthreads();

    // out[b, p, c0+c] = acc[c*57 + p]; 8 contiguous floats per p-row
    float* __restrict__ ob = out + (size_t)b * 49 * CCH + c0;
    #pragma unroll
    for (int i = tid; i < 49 * TILE_C; i += 256) {
        const int p = i >> 3;              // 0..48
        const int c = i & (TILE_C - 1);    // 0..7
        ob[p * CCH + c] = acc[c * ACC_STRIDE + p];
    }
}

extern "C" void kernel_launch(void* const* d_in, const int* in_sizes, int n_in,
                              void* d_out, int out_size) {
    const float* x = (const float*)d_in[0];
    float* out = (float*)d_out;
    dim3 grid(CCH / TILE_C, 32);   // (256, 32) = 8192 short blocks
    upp_pool_kernel<<<grid, 256>>>(x, out);
}